// round 1
// baseline (speedup 1.0000x reference)
#include <cuda_runtime.h>
#include <cuda_pipeline.h>
#include <math.h>

#define BATCH 16
#define NN    2048
#define KH    12
#define FD    128
#define OD    64

#define NT 16   // n values per block (main kernel)
#define NS 4    // n slices processed per phase

// attention scratch: att[2][NN][6][6]
__device__ float g_att[2 * NN * 36];

// ---------------------------------------------------------------------------
// Kernel A: compute attention matrices.
//   s1[q] = (h[i,n,i*6+q] @ W) @ a1 = h[i,n,i*6+q] @ (W @ a1)   (reassociated)
//   e[p,q] = leaky_relu(s1[p] + s2[q], 0.2); mask by adj[i]; softmax rows.
// Note: e[i] in the reference picks BATCH i, so att depends only on (i, n).
// ---------------------------------------------------------------------------
__global__ void __launch_bounds__(192) attn_scores_kernel(
    const float* __restrict__ h, const int* __restrict__ adj,
    const float* __restrict__ W, const float* __restrict__ a)
{
    const int i = blockIdx.y;   // group / batch index (0 or 1)
    const int n = blockIdx.x;
    __shared__ float wa1[FD], wa2[FD];
    __shared__ float s1[6], s2[6], ev[36];
    const int t = threadIdx.x;

    if (t < FD) {
        float r1 = 0.f, r2 = 0.f;
        const float* wr = W + t * OD;
        const float* ap = a + i * 2 * OD;
        #pragma unroll 16
        for (int o = 0; o < OD; ++o) {
            const float w = wr[o];
            r1 = fmaf(w, ap[o], r1);
            r2 = fmaf(w, ap[OD + o], r2);
        }
        wa1[t] = r1; wa2[t] = r2;
    }
    __syncthreads();

    {   // 6 warps: warp q computes s1[q], s2[q]
        const int q = t >> 5, l = t & 31;
        const float* hp = h + (((size_t)i * NN + n) * KH + (i * 6 + q)) * FD;
        float p1 = 0.f, p2 = 0.f;
        #pragma unroll
        for (int f = l; f < FD; f += 32) {
            const float hv = hp[f];
            p1 = fmaf(hv, wa1[f], p1);
            p2 = fmaf(hv, wa2[f], p2);
        }
        #pragma unroll
        for (int off = 16; off > 0; off >>= 1) {
            p1 += __shfl_down_sync(0xffffffffu, p1, off);
            p2 += __shfl_down_sync(0xffffffffu, p2, off);
        }
        if (l == 0) { s1[q] = p1; s2[q] = p2; }
    }
    __syncthreads();

    if (t < 36) {
        const int p = t / 6, q = t - p * 6;
        float v = s1[p] + s2[q];
        v = v > 0.f ? v : 0.2f * v;            // leaky_relu(0.2)
        if (adj[i * 36 + t] <= 0) v = -9.0e15f;
        ev[t] = v;
    }
    __syncthreads();

    if (t < 6) {
        const float* row = ev + t * 6;
        float m = row[0];
        #pragma unroll
        for (int q = 1; q < 6; ++q) m = fmaxf(m, row[q]);
        float ex[6]; float sum = 0.f;
        #pragma unroll
        for (int q = 0; q < 6; ++q) { ex[q] = expf(row[q] - m); sum += ex[q]; }
        const float inv = 1.f / sum;
        float* dst = g_att + ((size_t)i * NN + n) * 36 + t * 6;
        #pragma unroll
        for (int q = 0; q < 6; ++q) dst[q] = ex[q] * inv;
    }
}

// ---------------------------------------------------------------------------
// Kernel B: out = elu( (att-premixed h) @ W )
//   premix:  Am[p,f] = sum_q att[i(p)][n][p%6][q] * h[b,n,i(p)*6+q,f]
//   matmul:  out[b,n,p,:] = elu( Am[p,:] @ W )
// Am is stored DUPLICATED ((v,v) pairs) in smem so fma.rn.f32x2 gets its
// broadcast operand from a single LDS.128 — no splat MOVs on the ALU pipe.
// ---------------------------------------------------------------------------

// shared-memory float offsets
#define SM_W    0                 // 128*64        = 8192 floats
#define SM_ASR  8192              // NS*12*128     = 6144 floats (raw h tiles)
#define SM_AMD  14336             // NS*12*256     = 12288 floats (dup premixed)
#define SM_ATT  26624             // 2 * NS*72     = 576 floats (att dbl-buf)
#define SM_TOTAL 27200            // floats -> 108800 bytes

__global__ void __launch_bounds__(192) gat_main_kernel(
    const float* __restrict__ h, const float* __restrict__ W,
    float* __restrict__ out)
{
    extern __shared__ float sm[];
    float* Wsm  = sm + SM_W;
    float* Asr  = sm + SM_ASR;
    float* Amd  = sm + SM_AMD;
    float* attb = sm + SM_ATT;

    const int t  = threadIdx.x;
    const int b  = blockIdx.y;
    const int n0 = blockIdx.x * NT;

    // ---- async load of W tile + phase 0 (h rows + att) ----
    auto load_phase = [&](int phn, int buf) {
        const int nbase = n0 + phn * NS;
        for (int idx = t; idx < NS * 384; idx += 192) {   // 1536 float4
            const int slc = idx / 384;
            const int r   = idx - slc * 384;
            __pipeline_memcpy_async(
                (float4*)Asr + idx,
                (const float4*)h + ((size_t)(b * NN + nbase + slc)) * 384 + r, 16);
        }
        for (int idx = t; idx < NS * 72; idx += 192) {    // 288 floats
            const int slc = idx / 72;
            const int j   = idx - slc * 72;
            const int gi  = j / 36;
            const int s   = j - gi * 36;
            __pipeline_memcpy_async(
                attb + buf * (NS * 72) + idx,
                g_att + ((size_t)gi * NN + nbase + slc) * 36 + s, 4);
        }
    };

    for (int idx = t; idx < 2048; idx += 192)
        __pipeline_memcpy_async((float4*)Wsm + idx, (const float4*)W + idx, 16);
    load_phase(0, 0);
    __pipeline_commit();
    __pipeline_wait_prior(0);
    __syncthreads();

    // matmul thread roles: 4 slices x (3 row-groups x 16 o-groups)
    const int sl  = t / 48;
    const int s48 = t - sl * 48;
    const int og  = s48 & 15;     // owns output cols og*4 .. og*4+3
    const int rg  = s48 >> 4;     // owns output rows rg*4 .. rg*4+3

    for (int ph = 0; ph < NT / NS; ++ph) {
        const int buf = ph & 1;

        // ---- premix: Amd (duplicated pairs) from Asr x att ----
        #pragma unroll
        for (int it = 0; it < 8; ++it) {
            const int idx = t + it * 192;             // 0..1535 (float4 granules)
            const int slc = idx / 384;
            const int r   = idx - slc * 384;
            const int p   = r >> 5;
            const int c   = r & 31;
            const int gi  = p / 6;
            const int p6  = p - gi * 6;
            const float* at = attb + buf * (NS * 72) + slc * 72 + gi * 36 + p6 * 6;
            const float4* arow = (const float4*)(Asr + (slc * 12 + gi * 6) * FD) + c;
            float4 acc = make_float4(0.f, 0.f, 0.f, 0.f);
            #pragma unroll
            for (int q = 0; q < 6; ++q) {
                const float  aq = at[q];
                const float4 hv = arow[q * 32];
                acc.x = fmaf(aq, hv.x, acc.x);
                acc.y = fmaf(aq, hv.y, acc.y);
                acc.z = fmaf(aq, hv.z, acc.z);
                acc.w = fmaf(aq, hv.w, acc.w);
            }
            float* dst = Amd + (slc * 12 + p) * 256 + c * 8;
            ((float4*)dst)[0] = make_float4(acc.x, acc.x, acc.y, acc.y);
            ((float4*)dst)[1] = make_float4(acc.z, acc.z, acc.w, acc.w);
        }
        __syncthreads();

        // prefetch next phase under the matmul
        if (ph + 1 < NT / NS) {
            load_phase(ph + 1, buf ^ 1);
            __pipeline_commit();
        }

        // ---- matmul: 4x4 register tile, packed f32x2 FMAs ----
        unsigned long long acc0[4] = {0ull, 0ull, 0ull, 0ull};
        unsigned long long acc1[4] = {0ull, 0ull, 0ull, 0ull};
        const float* Abase = Amd + (sl * 12 + rg * 4) * 256;

        #pragma unroll 4
        for (int f4 = 0; f4 < 32; ++f4) {
            ulonglong2 alo[4], ahi[4];
            #pragma unroll
            for (int r = 0; r < 4; ++r) {
                const ulonglong2* ar =
                    (const ulonglong2*)(Abase + r * 256 + f4 * 8);
                alo[r] = ar[0];   // dup pairs for f, f+1
                ahi[r] = ar[1];   // dup pairs for f+2, f+3
            }
            #pragma unroll
            for (int j = 0; j < 4; ++j) {
                const ulonglong2 wv =
                    *(const ulonglong2*)(Wsm + (f4 * 4 + j) * OD + og * 4);
                #pragma unroll
                for (int r = 0; r < 4; ++r) {
                    const unsigned long long av =
                        (j == 0) ? alo[r].x : (j == 1) ? alo[r].y :
                        (j == 2) ? ahi[r].x : ahi[r].y;
                    asm("fma.rn.f32x2 %0, %1, %2, %0;"
                        : "+l"(acc0[r]) : "l"(av), "l"(wv.x));
                    asm("fma.rn.f32x2 %0, %1, %2, %0;"
                        : "+l"(acc1[r]) : "l"(av), "l"(wv.y));
                }
            }
        }

        // ---- epilogue: ELU + store straight from registers ----
        const int n = n0 + ph * NS + sl;
        #pragma unroll
        for (int r = 0; r < 4; ++r) {
            const int p = rg * 4 + r;
            const float2 v01 = *(const float2*)(&acc0[r]);
            const float2 v23 = *(const float2*)(&acc1[r]);
            float4 o4;
            o4.x = v01.x > 0.f ? v01.x : expm1f(v01.x);
            o4.y = v01.y > 0.f ? v01.y : expm1f(v01.y);
            o4.z = v23.x > 0.f ? v23.x : expm1f(v23.x);
            o4.w = v23.y > 0.f ? v23.y : expm1f(v23.y);
            *(float4*)(out + (((size_t)b * NN + n) * KH + p) * OD + og * 4) = o4;
        }

        __pipeline_wait_prior(0);
        __syncthreads();
    }
}

// ---------------------------------------------------------------------------
extern "C" void kernel_launch(void* const* d_in, const int* in_sizes, int n_in,
                              void* d_out, int out_size)
{
    (void)in_sizes; (void)n_in; (void)out_size;
    const float* h   = (const float*)d_in[0];
    const int*   adj = (const int*)d_in[1];
    const float* W   = (const float*)d_in[2];
    const float* a   = (const float*)d_in[3];
    float* out = (float*)d_out;

    attn_scores_kernel<<<dim3(NN, 2), 192>>>(h, adj, W, a);

    cudaFuncSetAttribute(gat_main_kernel,
                         cudaFuncAttributeMaxDynamicSharedMemorySize,
                         SM_TOTAL * (int)sizeof(float));
    gat_main_kernel<<<dim3(NN / NT, BATCH), 192, SM_TOTAL * sizeof(float)>>>(
        h, W, out);
}

// round 2
// speedup vs baseline: 1.8251x; 1.8251x over previous
#include <cuda_runtime.h>
#include <cuda_pipeline.h>
#include <math.h>

#define BATCH 16
#define NN    2048
#define KH    12
#define FD    128
#define OD    64

// attention scratch: att[2][NN][6][6]
__device__ float g_att[2 * NN * 36];

// ---------------------------------------------------------------------------
// Kernel A: attention matrices. One warp per (i, n).
//   s1[q] = h[i,n,i*6+q] @ (W @ a1)   (reassociated)
//   e[p,q] = leaky_relu(s1[p]+s2[q], 0.2), mask by adj[i], row-softmax.
// ---------------------------------------------------------------------------
__global__ void __launch_bounds__(256) attn_scores_kernel(
    const float* __restrict__ h, const int* __restrict__ adj,
    const float* __restrict__ W, const float* __restrict__ a)
{
    __shared__ float wa1[FD], wa2[FD];
    const int t = threadIdx.x;
    // all warps in a block share i: blocks 0..255 -> i=0, 256..511 -> i=1
    const int i = blockIdx.x >> 8;

    if (t < FD) {
        float r1 = 0.f, r2 = 0.f;
        const float* wr = W + t * OD;
        const float* ap = a + i * 2 * OD;
        #pragma unroll 16
        for (int o = 0; o < OD; ++o) {
            const float w = wr[o];
            r1 = fmaf(w, ap[o], r1);
            r2 = fmaf(w, ap[OD + o], r2);
        }
        wa1[t] = r1; wa2[t] = r2;
    }
    __syncthreads();

    const int wid = t >> 5, l = t & 31;
    const int n = ((blockIdx.x & 255) << 3) + wid;     // 0..2047

    float p1[6], p2[6];
    const float* hb = h + (((size_t)i * NN + n) * KH + i * 6) * FD;
    #pragma unroll
    for (int q = 0; q < 6; ++q) { p1[q] = 0.f; p2[q] = 0.f; }
    #pragma unroll
    for (int it = 0; it < 4; ++it) {
        const int f = l + it * 32;
        const float w1 = wa1[f], w2 = wa2[f];
        #pragma unroll
        for (int q = 0; q < 6; ++q) {
            const float hv = hb[q * FD + f];
            p1[q] = fmaf(hv, w1, p1[q]);
            p2[q] = fmaf(hv, w2, p2[q]);
        }
    }
    // butterfly: every lane gets full sums
    #pragma unroll
    for (int off = 16; off > 0; off >>= 1) {
        #pragma unroll
        for (int q = 0; q < 6; ++q) {
            p1[q] += __shfl_xor_sync(0xffffffffu, p1[q], off);
            p2[q] += __shfl_xor_sync(0xffffffffu, p2[q], off);
        }
    }

    if (l < 6) {   // lane p handles softmax row p
        const int p = l;
        float e[6];
        float m = -1e30f;
        #pragma unroll
        for (int q = 0; q < 6; ++q) {
            float v = p1[p] + p2[q];
            v = v > 0.f ? v : 0.2f * v;
            if (adj[i * 36 + p * 6 + q] <= 0) v = -9.0e15f;
            e[q] = v;
            m = fmaxf(m, v);
        }
        float sum = 0.f;
        #pragma unroll
        for (int q = 0; q < 6; ++q) { e[q] = expf(e[q] - m); sum += e[q]; }
        const float inv = 1.f / sum;
        float* dst = g_att + ((size_t)i * NN + n) * 36 + p * 6;
        #pragma unroll
        for (int q = 0; q < 6; ++q) dst[q] = e[q] * inv;
    }
}

// ---------------------------------------------------------------------------
// Kernel B: out = elu( postmix( h @ W ) )
// Each thread owns one (slice, group, colgroup): computes Wh[6 rows][4 cols]
// in f32x2 accumulators from RAW h rows (broadcast LDS) and W, then applies
// the 6x6 attention mix IN REGISTERS, then ELU + store. No premix smem pass.
// ---------------------------------------------------------------------------

#define NSL     4                    // n-slices per phase
#define PHASES  4
#define NT      (NSL * PHASES)       // 16 n per block
#define THREADS 128

// shared float offsets
#define SM_W    0                              // 8192 floats
#define SM_ASR  8192                           // 2 * NSL*12*128 = 12288
#define SM_ATT  (SM_ASR + 2 * NSL * KH * FD)   // 2 * NSL*72 = 576
#define SM_TOT  (SM_ATT + 2 * NSL * 72)

__device__ __forceinline__ unsigned long long splat2(float x) {
    unsigned long long d;
    asm("mov.b64 %0, {%1, %1};" : "=l"(d) : "f"(x));
    return d;
}
__device__ __forceinline__ void fma2(unsigned long long& acc,
                                     unsigned long long a, unsigned long long b) {
    asm("fma.rn.f32x2 %0, %1, %2, %0;" : "+l"(acc) : "l"(a), "l"(b));
}

__global__ void __launch_bounds__(THREADS) gat_main_kernel(
    const float* __restrict__ h, const float* __restrict__ W,
    float* __restrict__ out)
{
    extern __shared__ float sm[];
    float* Wsm  = sm + SM_W;
    float* Asr  = sm + SM_ASR;
    float* attb = sm + SM_ATT;

    const int t  = threadIdx.x;
    const int b  = blockIdx.y;
    const int n0 = blockIdx.x * NT;

    auto load_phase = [&](int phn, int buf) {
        const int nbase = n0 + phn * NSL;
        float4* dst = (float4*)(Asr + buf * (NSL * KH * FD));
        for (int idx = t; idx < NSL * 384; idx += THREADS) {   // 1536 float4
            const int slc = idx / 384;
            const int r   = idx - slc * 384;
            __pipeline_memcpy_async(
                dst + idx,
                (const float4*)h + ((size_t)(b * NN + nbase + slc)) * 384 + r, 16);
        }
        for (int idx = t; idx < NSL * 72; idx += THREADS) {
            const int slc = idx / 72;
            const int j   = idx - slc * 72;
            const int gi  = j / 36;
            const int s   = j - gi * 36;
            __pipeline_memcpy_async(
                attb + buf * (NSL * 72) + idx,
                g_att + ((size_t)gi * NN + nbase + slc) * 36 + s, 4);
        }
    };

    for (int idx = t; idx < 2048; idx += THREADS)
        __pipeline_memcpy_async((float4*)Wsm + idx, (const float4*)W + idx, 16);
    load_phase(0, 0);
    __pipeline_commit();
    __pipeline_wait_prior(0);
    __syncthreads();

    const int sl = t >> 5;            // slice 0..3 (one warp per slice)
    const int g  = (t >> 4) & 1;      // k-group 0/1
    const int cg = t & 15;            // output cols cg*4..cg*4+3

    for (int ph = 0; ph < PHASES; ++ph) {
        const int buf = ph & 1;

        // prefetch next phase (into other buffer) before the heavy loop
        if (ph + 1 < PHASES) {
            load_phase(ph + 1, buf ^ 1);
            __pipeline_commit();
        }

        const float* Ab = Asr + buf * (NSL * KH * FD) + (sl * KH + g * 6) * FD;

        unsigned long long acc[6][2];
        #pragma unroll
        for (int q = 0; q < 6; ++q) { acc[q][0] = 0ull; acc[q][1] = 0ull; }

        #pragma unroll 4
        for (int f4 = 0; f4 < 32; ++f4) {
            float4 a4[6];
            #pragma unroll
            for (int q = 0; q < 6; ++q)
                a4[q] = ((const float4*)(Ab + q * FD))[f4];
            #pragma unroll
            for (int j = 0; j < 4; ++j) {
                const ulonglong2 wv =
                    *(const ulonglong2*)(Wsm + (f4 * 4 + j) * OD + cg * 4);
                #pragma unroll
                for (int q = 0; q < 6; ++q) {
                    const float av = (j == 0) ? a4[q].x : (j == 1) ? a4[q].y :
                                     (j == 2) ? a4[q].z : a4[q].w;
                    const unsigned long long d = splat2(av);
                    fma2(acc[q][0], d, wv.x);
                    fma2(acc[q][1], d, wv.y);
                }
            }
        }

        // ---- register post-mix by att, then ELU + store ----
        const int n = n0 + ph * NSL + sl;
        const float* at = attb + buf * (NSL * 72) + sl * 72 + g * 36;
        #pragma unroll
        for (int p = 0; p < 6; ++p) {
            unsigned long long o0 = 0ull, o1 = 0ull;
            #pragma unroll
            for (int q = 0; q < 6; ++q) {
                const unsigned long long d = splat2(at[p * 6 + q]);
                fma2(o0, d, acc[q][0]);
                fma2(o1, d, acc[q][1]);
            }
            const float2 v01 = *(const float2*)(&o0);
            const float2 v23 = *(const float2*)(&o1);
            float4 o4;
            o4.x = v01.x > 0.f ? v01.x : expm1f(v01.x);
            o4.y = v01.y > 0.f ? v01.y : expm1f(v01.y);
            o4.z = v23.x > 0.f ? v23.x : expm1f(v23.x);
            o4.w = v23.y > 0.f ? v23.y : expm1f(v23.y);
            *(float4*)(out + (((size_t)b * NN + n) * KH + g * 6 + p) * OD
                       + cg * 4) = o4;
        }

        __pipeline_wait_prior(0);
        __syncthreads();
    }
}

// ---------------------------------------------------------------------------
extern "C" void kernel_launch(void* const* d_in, const int* in_sizes, int n_in,
                              void* d_out, int out_size)
{
    (void)in_sizes; (void)n_in; (void)out_size;
    const float* h   = (const float*)d_in[0];
    const int*   adj = (const int*)d_in[1];
    const float* W   = (const float*)d_in[2];
    const float* a   = (const float*)d_in[3];
    float* out = (float*)d_out;

    attn_scores_kernel<<<512, 256>>>(h, adj, W, a);

    cudaFuncSetAttribute(gat_main_kernel,
                         cudaFuncAttributeMaxDynamicSharedMemorySize,
                         SM_TOT * (int)sizeof(float));
    gat_main_kernel<<<dim3(NN / NT, BATCH), THREADS, SM_TOT * sizeof(float)>>>(
        h, W, out);
}